// round 15
// baseline (speedup 1.0000x reference)
#include <cuda_runtime.h>

// Problem constants (fixed by the dataset: H=W=128, C=100).
#define HH 128
#define WW 128
#define CC 100
#define TY 4            // tile rows per CTA -> 512 CTAs (3.46/SM, good balance)
#define TX 8            // tile cols per CTA
#define MDMAX 15
#define KMAX (2*MDMAX+1)        // 31
#define PWY_MAX (TY + 2*MDMAX)  // 34: max halo height
#define PWS 39                  // padded halo stride (odd -> conflict-free LDS.128)
#define MAXOBJ 4
#define NTHREADS 256            // 16 pixel-pairs * 16 dy-interleaved chunks
#define NCHUNK 16

// ---- static shared memory (~44 KB, fits default 48 KB) ----
__shared__ float4        g_smA[PWY_MAX * PWS];   // NEGATED prev ch0..3
__shared__ float4        g_smB[PWY_MAX * PWS];   // NEGATED prev ch4..7
__shared__ unsigned char g_smObj[PWY_MAX * PWS]; // object id or 255
__shared__ unsigned char g_rowU[PWY_MAX * TX];   // row-uniformity table
__shared__ int           g_sgt[MAXOBJ];

// ---- packed f32x2 helpers (sm_103a) ----
__device__ __forceinline__ unsigned long long f2_add(unsigned long long a, unsigned long long b) {
    unsigned long long r; asm("add.rn.f32x2 %0, %1, %2;" : "=l"(r) : "l"(a), "l"(b)); return r;
}
__device__ __forceinline__ unsigned long long f2_mul(unsigned long long a, unsigned long long b) {
    unsigned long long r; asm("mul.rn.f32x2 %0, %1, %2;" : "=l"(r) : "l"(a), "l"(b)); return r;
}
__device__ __forceinline__ unsigned long long f2_fma(unsigned long long a, unsigned long long b,
                                                     unsigned long long c) {
    unsigned long long r; asm("fma.rn.f32x2 %0, %1, %2, %3;" : "=l"(r) : "l"(a), "l"(b), "l"(c)); return r;
}
__device__ __forceinline__ float f2_hsum(unsigned long long v) {
    float lo, hi; asm("mov.b64 {%0, %1}, %2;" : "=f"(lo), "=f"(hi) : "l"(v)); return lo + hi;
}

// 4-channel partial distance; prev stored NEGATED so t = q + p.
__device__ __forceinline__ float d4p(const ulonglong2& q, const ulonglong2& p) {
    const unsigned long long t01 = f2_add(q.x, p.x);
    unsigned long long acc = f2_mul(t01, t01);
    const unsigned long long t23 = f2_add(q.y, p.y);
    acc = f2_fma(t23, t23, acc);
    return f2_hsum(acc);
}

// (d < 1.0f) as an all-ones/zero REGISTER (SASS FSET, 4-cyc, pred-as-data) —
// avoids the 13-cyc pred-as-guard FSETP->@P chain.
__device__ __forceinline__ unsigned setlt1(float d) {
    unsigned r; asm("set.lt.u32.f32 %0, %1, %2;" : "=r"(r) : "f"(d), "f"(1.0f));
    return r;
}

__device__ __forceinline__ float dist4s(float4 q, float4 p, float d) {
    float t0 = q.x - p.x, t1 = q.y - p.y, t2 = q.z - p.z, t3 = q.w - p.w;
    d = fmaf(t0, t0, d); d = fmaf(t1, t1, d); d = fmaf(t2, t2, d); d = fmaf(t3, t3, d);
    return d;
}
// negated-p variant for smem cells
__device__ __forceinline__ float dist4n(float4 q, float4 pn, float d) {
    float t0 = q.x + pn.x, t1 = q.y + pn.y, t2 = q.z + pn.z, t3 = q.w + pn.w;
    d = fmaf(t0, t0, d); d = fmaf(t1, t1, d); d = fmaf(t2, t2, d); d = fmaf(t3, t3, d);
    return d;
}

// Rare path: resolve survivors of the 4-channel filter for one pixel/row.
__device__ __forceinline__ void survivors(unsigned mask, int cellbase,
                                          const float* __restrict__ qpix,
                                          float* best,
                                          const float* __restrict__ prowpix)
{
    const float4 q0 = __ldg((const float4*)qpix);
    const float4 q1 = __ldg((const float4*)(qpix + 4));
    do {
        const int dx = __ffs(mask) - 1;
        mask &= mask - 1;
        const int cell = cellbase + dx;
        const int o = (int)g_smObj[cell];
        if (o == 255) continue;
        float d = dist4n(q0, g_smA[cell], 0.0f);
        d = dist4n(q1, g_smB[cell], d);
        float b = 1.0f;
        #pragma unroll
        for (int t = 0; t < MAXOBJ; t++) if (o == t) b = best[t];
        if (d < b) {
            const float* pg = prowpix + dx * CC;
            #pragma unroll 1
            for (int c = 8; c < CC; c += 4) {
                const float4 pv = __ldg((const float4*)(pg + c));
                const float4 qv = __ldg((const float4*)(qpix + c));
                d = dist4s(qv, pv, d);
                if (d >= b) break;              // monotone partial: exact skip
            }
            if (d < b) {
                #pragma unroll
                for (int t = 0; t < MAXOBJ; t++) if (o == t) best[t] = d;
            }
        }
    } while (mask);
}

// Whole-window-uniform case: exact UNCLAMPED min over this thread's rows.
__device__ __forceinline__ float uni_min(const float* __restrict__ prev,
                                         const float* __restrict__ qpix,
                                         int gy, int gx, int md, int K, int chunk)
{
    float m = 3.402823466e38f;
    for (int i = 0; i < 2; i++) {
        const int dy = chunk + NCHUNK * i;
        if (dy >= K) break;
        for (int dx = 0; dx < K; dx++) {
            const float* pg = prev + ((gy + dy - md) * WW + (gx + dx - md)) * CC;
            float d = 0.0f;
            #pragma unroll 1
            for (int c = 0; c < CC; c += 4) {
                const float4 pv = __ldg((const float4*)(pg + c));
                const float4 qv = __ldg((const float4*)(qpix + c));
                d = dist4s(qv, pv, d);
                if (d >= m) break;
            }
            if (d < m) m = d;
        }
    }
    return m;
}

__device__ __forceinline__ int merge_u(int a, int b) {
    // -1 = none seen, 255 = broken, else object id
    return (a == -1) ? b : ((b == -1 || b == a) ? a : 255);
}

// KC = compile-time K (31) or 0 => runtime Krt (md < 15).
template <int KC>
__device__ __forceinline__ void fast_body(
    const float* __restrict__ prev, const float* __restrict__ query,
    const int* __restrict__ labels, const int* __restrict__ gt,
    float* __restrict__ out, int nobj, int md, int Krt)
{
    const int K   = KC ? KC : Krt;
    const int PWX = TX + 2 * md;
    const int PWY = TY + 2 * md;

    const int tid   = threadIdx.x;
    const int tileX = blockIdx.x * TX;
    const int tileY = blockIdx.y * TY;

    if (tid < MAXOBJ) g_sgt[tid] = (tid < nobj) ? gt[tid] : 0x7fffffff;
    __syncthreads();

    // ---- halo load: object id + NEGATED first 8 channels of prev embedding ----
    for (int i = tid; i < PWY * PWX; i += NTHREADS) {
        const int sy = i / PWX, sx = i - sy * PWX;
        const int hy = tileY + sy - md, hx = tileX + sx - md;
        int o = 255;
        float4 a = make_float4(0.f, 0.f, 0.f, 0.f), b = a;
        if (hy >= 0 && hy < HH && hx >= 0 && hx < WW) {
            const int lab = labels[hy * WW + hx];
            #pragma unroll
            for (int t = 0; t < MAXOBJ; t++) if (g_sgt[t] == lab) o = t;
            const float4* pp = (const float4*)(prev + (hy * WW + hx) * CC);
            const float4 a0 = pp[0], b0 = pp[1];
            a = make_float4(-a0.x, -a0.y, -a0.z, -a0.w);
            b = make_float4(-b0.x, -b0.y, -b0.z, -b0.w);
        }
        const int si = sy * PWS + sx;
        g_smA[si] = a;
        g_smB[si] = b;
        g_smObj[si] = (unsigned char)o;
    }
    __syncthreads();

    // ---- rowU[sy][px]: uniform object over g_smObj[sy][px .. px+K) or 255 ----
    for (int i = tid; i < PWY * TX; i += NTHREADS) {
        const int sy = i >> 3, px = i & 7;
        const unsigned char* r = g_smObj + sy * PWS + px;
        int v = r[0];
        for (int j = 1; j < K; j++) if ((int)r[j] != v) v = 255;
        g_rowU[i] = (unsigned char)v;
    }
    __syncthreads();

    // Thread = (pixel-pair, dy-chunk). 16 pairs x 16 chunks.
    const int pairIdx = tid >> 4;
    const int chunk   = tid & 15;
    const int py  = pairIdx >> 2;
    const int pxE = (pairIdx & 3) << 1;         // even pixel x in tile
    const int gy  = tileY + py;
    const int gxE = tileX + pxE;
    const float* qpE = query + (gy * WW + gxE) * CC;
    const float* qpO = qpE + CC;                // adjacent pixel (gxE+1)
    const ulonglong2 qAE = ((const ulonglong2*)qpE)[0];
    const ulonglong2 qAO = ((const ulonglong2*)qpO)[0];

    float bestE[MAXOBJ], bestO[MAXOBJ];
    #pragma unroll
    for (int t = 0; t < MAXOBJ; t++) { bestE[t] = 1.0f; bestO[t] = 1.0f; }
    int vE = -1, vO = -1;

    for (int it = 0; it < 2; it++) {
        const int dy = chunk + NCHUNK * it;     // stride-16 row interleave
        if (dy >= K) break;
        vE = merge_u(vE, (int)g_rowU[(py + dy) * TX + pxE]);
        vO = merge_u(vO, (int)g_rowU[(py + dy) * TX + pxE + 1]);

        const int base = (py + dy) * PWS + pxE;
        const ulonglong2* rp = (const ulonglong2*)g_smA + base;

        // ---- stage 1: shared-cell branchless survivor masks for BOTH pixels ----
        unsigned mE = 0, mO = 0;
        if (KC) {
            #pragma unroll
            for (int c = 0; c <= KC; c++) {
                const ulonglong2 p = rp[c];
                if (c < KC) mE |= setlt1(d4p(qAE, p)) & (1u << c);
                if (c > 0)  mO |= setlt1(d4p(qAO, p)) & (1u << (c - 1));
            }
        } else {
            for (int c = 0; c <= K; c++) {
                const ulonglong2 p = rp[c];
                if (c < K) mE |= setlt1(d4p(qAE, p)) & (1u << c);
                if (c > 0) mO |= setlt1(d4p(qAO, p)) & (1u << (c - 1));
            }
        }

        // ---- stage 2/3: rare survivors ----
        if (mE | mO) {
            const float* prowE = prev + ((gy + dy - md) * WW + (gxE - md)) * CC;
            if (mE) survivors(mE, base,     qpE, bestE, prowE);
            if (mO) survivors(mO, base + 1, qpO, bestO, prowE + CC);
        }
    }

    // ---- combine the 16 chunk lanes of each pixel (all lanes converged) ----
    #pragma unroll
    for (int t = 0; t < MAXOBJ; t++) {
        #pragma unroll
        for (int s = 1; s <= 8; s <<= 1) {
            bestE[t] = fminf(bestE[t], __shfl_xor_sync(0xffffffffu, bestE[t], s));
            bestO[t] = fminf(bestO[t], __shfl_xor_sync(0xffffffffu, bestO[t], s));
        }
    }
    #pragma unroll
    for (int s = 1; s <= 8; s <<= 1) {
        vE = merge_u(vE, __shfl_xor_sync(0xffffffffu, vE, s));
        vO = merge_u(vO, __shfl_xor_sync(0xffffffffu, vO, s));
    }

    // ---- whole-window-uniform pixels: exact unclamped recompute (rare) ----
    const unsigned hm = 0xFFFFu << ((tid & 31) & 16);   // this thread's 16-lane half
    if (vE >= 0 && vE < MAXOBJ) {
        float m = uni_min(prev, qpE, gy, gxE, md, K, chunk);
        #pragma unroll
        for (int s = 1; s <= 8; s <<= 1) m = fminf(m, __shfl_xor_sync(hm, m, s));
        #pragma unroll
        for (int t = 0; t < MAXOBJ; t++) if (vE == t) bestE[t] = m;
    }
    if (vO >= 0 && vO < MAXOBJ) {
        float m = uni_min(prev, qpO, gy, gxE + 1, md, K, chunk);
        #pragma unroll
        for (int s = 1; s <= 8; s <<= 1) m = fminf(m, __shfl_xor_sync(hm, m, s));
        #pragma unroll
        for (int t = 0; t < MAXOBJ; t++) if (vO == t) bestO[t] = m;
    }

    if (chunk == 0) {
        float* opE = out + (gy * WW + gxE) * nobj;
        float* opO = opE + nobj;
        #pragma unroll
        for (int t = 0; t < MAXOBJ; t++)
            if (t < nobj) { opE[t] = bestE[t]; opO[t] = bestO[t]; }
    }
}

__global__ __launch_bounds__(NTHREADS, 4)
void IntVOS_27015344292341_kernel(const float* __restrict__ prev,
                                  const float* __restrict__ query,
                                  const int*   __restrict__ labels,
                                  const int*   __restrict__ gt,
                                  const int*   __restrict__ mdp,
                                  float*       __restrict__ out,
                                  int nobj)
{
    const int md = mdp ? mdp[0] : MDMAX;
    const int K  = 2 * md + 1;

    if (md <= MDMAX && nobj <= MAXOBJ && nobj > 0) {
        if (md == MDMAX)
            fast_body<KMAX>(prev, query, labels, gt, out, nobj, md, K);
        else
            fast_body<0>(prev, query, labels, gt, out, nobj, md, K);
        return;
    }

    // ---------------- generic fallback (md > 15 or nobj > 4): one thread/pixel ----------------
    const int tid = threadIdx.x;
    if (tid >= TY * TX) return;
    const int py = tid >> 3, px = tid & 7;
    const int gy = blockIdx.y * TY + py, gx = blockIdx.x * TX + px;
    const float* qp = query + (gy * WW + gx) * CC;

    const int NB = 32;
    float best[NB];
    const int no = (nobj < NB) ? nobj : NB;
    for (int t = 0; t < no; t++) best[t] = 1.0f;
    int u = -1, allm = 1;

    for (int dy = 0; dy < K; ++dy) {
        for (int dx = 0; dx < K; ++dx) {
            const int ny = gy + dy - md, nx = gx + dx - md;
            if (ny < 0 || ny >= HH || nx < 0 || nx >= WW) { allm = 0; continue; }
            const int lab = labels[ny * WW + nx];
            int o = -1;
            for (int t = 0; t < no; t++) if (__ldg(gt + t) == lab) o = t;
            if (o < 0) { allm = 0; continue; }
            if (u < 0) u = o; else if (o != u) allm = 0;
            const float b = best[o];
            const float* pg = prev + (ny * WW + nx) * CC;
            float d = 0.0f;
            for (int c = 0; c < CC; c += 4) {
                const float4 pv = __ldg((const float4*)(pg + c));
                const float4 qv = __ldg((const float4*)(qp + c));
                d = dist4s(qv, pv, d);
                if (d >= b) break;
            }
            if (d < b) best[o] = d;
        }
    }
    if (allm && u >= 0) {
        float m = 3.402823466e38f;
        for (int dy = 0; dy < K; ++dy) {
            for (int dx = 0; dx < K; ++dx) {
                const float* pg = prev + ((gy + dy - md) * WW + (gx + dx - md)) * CC;
                float d = 0.0f;
                for (int c = 0; c < CC; c += 4) {
                    const float4 pv = __ldg((const float4*)(pg + c));
                    const float4 qv = __ldg((const float4*)(qp + c));
                    d = dist4s(qv, pv, d);
                    if (d >= m) break;
                }
                if (d < m) m = d;
            }
        }
        best[u] = m;
    }
    float* op = out + (gy * WW + gx) * nobj;
    for (int t = 0; t < no; t++) op[t] = best[t];
    for (int t = no; t < nobj; t++) op[t] = 1.0f;
}

extern "C" void kernel_launch(void* const* d_in, const int* in_sizes, int n_in,
                              void* d_out, int out_size) {
    // metadata order: prev_frame_embedding, query_embedding, prev_frame_labels,
    //                 gt_ids, max_distance
    const float* prev   = (const float*)d_in[0];
    const float* query  = (const float*)d_in[1];
    const int*   labels = (const int*)d_in[2];
    const int*   gt     = (const int*)d_in[3];
    const int*   mdp    = (n_in >= 5) ? (const int*)d_in[4] : nullptr;
    const int    nobj   = in_sizes[3];

    dim3 grid(WW / TX, HH / TY);   // 16 x 32 = 512 CTAs
    IntVOS_27015344292341_kernel<<<grid, NTHREADS>>>(
        prev, query, labels, gt, mdp, (float*)d_out, nobj);
}

// round 16
// speedup vs baseline: 1.0026x; 1.0026x over previous
#include <cuda_runtime.h>

// Problem constants (fixed by the dataset: H=W=128, C=100).
#define HH 128
#define WW 128
#define CC 100
#define TY 4            // tile rows per CTA -> 512 CTAs (3.46/SM, good balance)
#define TX 8            // tile cols per CTA
#define MDMAX 15
#define KMAX (2*MDMAX+1)        // 31
#define PWY_MAX (TY + 2*MDMAX)  // 34: max halo height
#define PWS 39                  // padded halo stride (odd -> conflict-free LDS.128)
#define MAXOBJ 4
#define NTHREADS 256            // 16 pixel-pairs * 16 dy-interleaved chunks
#define NCHUNK 16

// ---- static shared memory (~44 KB, fits default 48 KB) ----
__shared__ float4        g_smA[PWY_MAX * PWS];   // NEGATED prev ch0..3
__shared__ float4        g_smB[PWY_MAX * PWS];   // NEGATED prev ch4..7
__shared__ unsigned char g_smObj[PWY_MAX * PWS]; // object id or 255
__shared__ unsigned char g_rowU[PWY_MAX * TX];   // row-uniformity table
__shared__ int           g_sgt[MAXOBJ];

// ---- packed f32x2 helpers (sm_103a) ----
__device__ __forceinline__ unsigned long long f2_add(unsigned long long a, unsigned long long b) {
    unsigned long long r; asm("add.rn.f32x2 %0, %1, %2;" : "=l"(r) : "l"(a), "l"(b)); return r;
}
__device__ __forceinline__ unsigned long long f2_mul(unsigned long long a, unsigned long long b) {
    unsigned long long r; asm("mul.rn.f32x2 %0, %1, %2;" : "=l"(r) : "l"(a), "l"(b)); return r;
}
__device__ __forceinline__ unsigned long long f2_fma(unsigned long long a, unsigned long long b,
                                                     unsigned long long c) {
    unsigned long long r; asm("fma.rn.f32x2 %0, %1, %2, %3;" : "=l"(r) : "l"(a), "l"(b), "l"(c)); return r;
}
__device__ __forceinline__ float f2_hsum(unsigned long long v) {
    float lo, hi; asm("mov.b64 {%0, %1}, %2;" : "=f"(lo), "=f"(hi) : "l"(v)); return lo + hi;
}

// 4-channel partial distance; prev stored NEGATED so t = q + p.
__device__ __forceinline__ float d4p(const ulonglong2& q, const ulonglong2& p) {
    const unsigned long long t01 = f2_add(q.x, p.x);
    unsigned long long acc = f2_mul(t01, t01);
    const unsigned long long t23 = f2_add(q.y, p.y);
    acc = f2_fma(t23, t23, acc);
    return f2_hsum(acc);
}

// (d < 1.0f) as an all-ones/zero REGISTER (SASS FSET, 4-cyc, pred-as-data) —
// avoids the 13-cyc pred-as-guard FSETP->@P chain.
__device__ __forceinline__ unsigned setlt1(float d) {
    unsigned r; asm("set.lt.u32.f32 %0, %1, %2;" : "=r"(r) : "f"(d), "f"(1.0f));
    return r;
}

__device__ __forceinline__ float dist4s(float4 q, float4 p, float d) {
    float t0 = q.x - p.x, t1 = q.y - p.y, t2 = q.z - p.z, t3 = q.w - p.w;
    d = fmaf(t0, t0, d); d = fmaf(t1, t1, d); d = fmaf(t2, t2, d); d = fmaf(t3, t3, d);
    return d;
}
// negated-p variant for smem cells
__device__ __forceinline__ float dist4n(float4 q, float4 pn, float d) {
    float t0 = q.x + pn.x, t1 = q.y + pn.y, t2 = q.z + pn.z, t3 = q.w + pn.w;
    d = fmaf(t0, t0, d); d = fmaf(t1, t1, d); d = fmaf(t2, t2, d); d = fmaf(t3, t3, d);
    return d;
}

// Rare path: resolve survivors of the 4-channel filter for one pixel/row.
__device__ __forceinline__ void survivors(unsigned mask, int cellbase,
                                          const float* __restrict__ qpix,
                                          float* best,
                                          const float* __restrict__ prowpix)
{
    const float4 q0 = __ldg((const float4*)qpix);
    const float4 q1 = __ldg((const float4*)(qpix + 4));
    do {
        const int dx = __ffs(mask) - 1;
        mask &= mask - 1;
        const int cell = cellbase + dx;
        const int o = (int)g_smObj[cell];
        if (o == 255) continue;
        float d = dist4n(q0, g_smA[cell], 0.0f);
        d = dist4n(q1, g_smB[cell], d);
        float b = 1.0f;
        #pragma unroll
        for (int t = 0; t < MAXOBJ; t++) if (o == t) b = best[t];
        if (d < b) {
            const float* pg = prowpix + dx * CC;
            #pragma unroll 1
            for (int c = 8; c < CC; c += 4) {
                const float4 pv = __ldg((const float4*)(pg + c));
                const float4 qv = __ldg((const float4*)(qpix + c));
                d = dist4s(qv, pv, d);
                if (d >= b) break;              // monotone partial: exact skip
            }
            if (d < b) {
                #pragma unroll
                for (int t = 0; t < MAXOBJ; t++) if (o == t) best[t] = d;
            }
        }
    } while (mask);
}

// Whole-window-uniform case: exact UNCLAMPED min over this thread's rows.
__device__ __forceinline__ float uni_min(const float* __restrict__ prev,
                                         const float* __restrict__ qpix,
                                         int gy, int gx, int md, int K, int chunk)
{
    float m = 3.402823466e38f;
    for (int i = 0; i < 2; i++) {
        const int dy = chunk + NCHUNK * i;
        if (dy >= K) break;
        for (int dx = 0; dx < K; dx++) {
            const float* pg = prev + ((gy + dy - md) * WW + (gx + dx - md)) * CC;
            float d = 0.0f;
            #pragma unroll 1
            for (int c = 0; c < CC; c += 4) {
                const float4 pv = __ldg((const float4*)(pg + c));
                const float4 qv = __ldg((const float4*)(qpix + c));
                d = dist4s(qv, pv, d);
                if (d >= m) break;
            }
            if (d < m) m = d;
        }
    }
    return m;
}

__device__ __forceinline__ int merge_u(int a, int b) {
    // -1 = none seen, 255 = broken, else object id
    return (a == -1) ? b : ((b == -1 || b == a) ? a : 255);
}

// KC = compile-time K (31) or 0 => runtime Krt (md < 15).
template <int KC>
__device__ __forceinline__ void fast_body(
    const float* __restrict__ prev, const float* __restrict__ query,
    const int* __restrict__ labels, const int* __restrict__ gt,
    float* __restrict__ out, int nobj, int md, int Krt)
{
    const int K   = KC ? KC : Krt;
    const int PWX = TX + 2 * md;
    const int PWY = TY + 2 * md;

    const int tid   = threadIdx.x;
    const int tileX = blockIdx.x * TX;
    const int tileY = blockIdx.y * TY;

    if (tid < MAXOBJ) g_sgt[tid] = (tid < nobj) ? gt[tid] : 0x7fffffff;
    __syncthreads();

    // ---- halo load: object id + NEGATED first 8 channels of prev embedding ----
    for (int i = tid; i < PWY * PWX; i += NTHREADS) {
        const int sy = i / PWX, sx = i - sy * PWX;
        const int hy = tileY + sy - md, hx = tileX + sx - md;
        int o = 255;
        float4 a = make_float4(0.f, 0.f, 0.f, 0.f), b = a;
        if (hy >= 0 && hy < HH && hx >= 0 && hx < WW) {
            const int lab = labels[hy * WW + hx];
            #pragma unroll
            for (int t = 0; t < MAXOBJ; t++) if (g_sgt[t] == lab) o = t;
            const float4* pp = (const float4*)(prev + (hy * WW + hx) * CC);
            const float4 a0 = pp[0], b0 = pp[1];
            a = make_float4(-a0.x, -a0.y, -a0.z, -a0.w);
            b = make_float4(-b0.x, -b0.y, -b0.z, -b0.w);
        }
        const int si = sy * PWS + sx;
        g_smA[si] = a;
        g_smB[si] = b;
        g_smObj[si] = (unsigned char)o;
    }
    __syncthreads();

    // ---- rowU[sy][px]: uniform object over g_smObj[sy][px .. px+K) or 255 ----
    for (int i = tid; i < PWY * TX; i += NTHREADS) {
        const int sy = i >> 3, px = i & 7;
        const unsigned char* r = g_smObj + sy * PWS + px;
        int v = r[0];
        for (int j = 1; j < K; j++) if ((int)r[j] != v) v = 255;
        g_rowU[i] = (unsigned char)v;
    }
    __syncthreads();

    // Thread = (pixel-pair, dy-chunk). 16 pairs x 16 chunks.
    const int pairIdx = tid >> 4;
    const int chunk   = tid & 15;
    const int py  = pairIdx >> 2;
    const int pxE = (pairIdx & 3) << 1;         // even pixel x in tile
    const int gy  = tileY + py;
    const int gxE = tileX + pxE;
    const float* qpE = query + (gy * WW + gxE) * CC;
    const float* qpO = qpE + CC;                // adjacent pixel (gxE+1)
    const ulonglong2 qAE = ((const ulonglong2*)qpE)[0];
    const ulonglong2 qAO = ((const ulonglong2*)qpO)[0];

    float bestE[MAXOBJ], bestO[MAXOBJ];
    #pragma unroll
    for (int t = 0; t < MAXOBJ; t++) { bestE[t] = 1.0f; bestO[t] = 1.0f; }
    int vE = -1, vO = -1;

    for (int it = 0; it < 2; it++) {
        const int dy = chunk + NCHUNK * it;     // stride-16 row interleave
        if (dy >= K) break;
        vE = merge_u(vE, (int)g_rowU[(py + dy) * TX + pxE]);
        vO = merge_u(vO, (int)g_rowU[(py + dy) * TX + pxE + 1]);

        const int base = (py + dy) * PWS + pxE;
        const ulonglong2* rp = (const ulonglong2*)g_smA + base;

        // ---- stage 1: shared-cell branchless survivor masks for BOTH pixels ----
        unsigned mE = 0, mO = 0;
        if (KC) {
            #pragma unroll
            for (int c = 0; c <= KC; c++) {
                const ulonglong2 p = rp[c];
                if (c < KC) mE |= setlt1(d4p(qAE, p)) & (1u << c);
                if (c > 0)  mO |= setlt1(d4p(qAO, p)) & (1u << (c - 1));
            }
        } else {
            for (int c = 0; c <= K; c++) {
                const ulonglong2 p = rp[c];
                if (c < K) mE |= setlt1(d4p(qAE, p)) & (1u << c);
                if (c > 0) mO |= setlt1(d4p(qAO, p)) & (1u << (c - 1));
            }
        }

        // ---- stage 2/3: rare survivors ----
        if (mE | mO) {
            const float* prowE = prev + ((gy + dy - md) * WW + (gxE - md)) * CC;
            if (mE) survivors(mE, base,     qpE, bestE, prowE);
            if (mO) survivors(mO, base + 1, qpO, bestO, prowE + CC);
        }
    }

    // ---- combine the 16 chunk lanes of each pixel (all lanes converged) ----
    #pragma unroll
    for (int t = 0; t < MAXOBJ; t++) {
        #pragma unroll
        for (int s = 1; s <= 8; s <<= 1) {
            bestE[t] = fminf(bestE[t], __shfl_xor_sync(0xffffffffu, bestE[t], s));
            bestO[t] = fminf(bestO[t], __shfl_xor_sync(0xffffffffu, bestO[t], s));
        }
    }
    #pragma unroll
    for (int s = 1; s <= 8; s <<= 1) {
        vE = merge_u(vE, __shfl_xor_sync(0xffffffffu, vE, s));
        vO = merge_u(vO, __shfl_xor_sync(0xffffffffu, vO, s));
    }

    // ---- whole-window-uniform pixels: exact unclamped recompute (rare) ----
    const unsigned hm = 0xFFFFu << ((tid & 31) & 16);   // this thread's 16-lane half
    if (vE >= 0 && vE < MAXOBJ) {
        float m = uni_min(prev, qpE, gy, gxE, md, K, chunk);
        #pragma unroll
        for (int s = 1; s <= 8; s <<= 1) m = fminf(m, __shfl_xor_sync(hm, m, s));
        #pragma unroll
        for (int t = 0; t < MAXOBJ; t++) if (vE == t) bestE[t] = m;
    }
    if (vO >= 0 && vO < MAXOBJ) {
        float m = uni_min(prev, qpO, gy, gxE + 1, md, K, chunk);
        #pragma unroll
        for (int s = 1; s <= 8; s <<= 1) m = fminf(m, __shfl_xor_sync(hm, m, s));
        #pragma unroll
        for (int t = 0; t < MAXOBJ; t++) if (vO == t) bestO[t] = m;
    }

    if (chunk == 0) {
        float* opE = out + (gy * WW + gxE) * nobj;
        float* opO = opE + nobj;
        #pragma unroll
        for (int t = 0; t < MAXOBJ; t++)
            if (t < nobj) { opE[t] = bestE[t]; opO[t] = bestO[t]; }
    }
}

__global__ __launch_bounds__(NTHREADS, 4)
void IntVOS_27015344292341_kernel(const float* __restrict__ prev,
                                  const float* __restrict__ query,
                                  const int*   __restrict__ labels,
                                  const int*   __restrict__ gt,
                                  const int*   __restrict__ mdp,
                                  float*       __restrict__ out,
                                  int nobj)
{
    const int md = mdp ? mdp[0] : MDMAX;
    const int K  = 2 * md + 1;

    if (md <= MDMAX && nobj <= MAXOBJ && nobj > 0) {
        if (md == MDMAX)
            fast_body<KMAX>(prev, query, labels, gt, out, nobj, md, K);
        else
            fast_body<0>(prev, query, labels, gt, out, nobj, md, K);
        return;
    }

    // ---------------- generic fallback (md > 15 or nobj > 4): one thread/pixel ----------------
    const int tid = threadIdx.x;
    if (tid >= TY * TX) return;
    const int py = tid >> 3, px = tid & 7;
    const int gy = blockIdx.y * TY + py, gx = blockIdx.x * TX + px;
    const float* qp = query + (gy * WW + gx) * CC;

    const int NB = 32;
    float best[NB];
    const int no = (nobj < NB) ? nobj : NB;
    for (int t = 0; t < no; t++) best[t] = 1.0f;
    int u = -1, allm = 1;

    for (int dy = 0; dy < K; ++dy) {
        for (int dx = 0; dx < K; ++dx) {
            const int ny = gy + dy - md, nx = gx + dx - md;
            if (ny < 0 || ny >= HH || nx < 0 || nx >= WW) { allm = 0; continue; }
            const int lab = labels[ny * WW + nx];
            int o = -1;
            for (int t = 0; t < no; t++) if (__ldg(gt + t) == lab) o = t;
            if (o < 0) { allm = 0; continue; }
            if (u < 0) u = o; else if (o != u) allm = 0;
            const float b = best[o];
            const float* pg = prev + (ny * WW + nx) * CC;
            float d = 0.0f;
            for (int c = 0; c < CC; c += 4) {
                const float4 pv = __ldg((const float4*)(pg + c));
                const float4 qv = __ldg((const float4*)(qp + c));
                d = dist4s(qv, pv, d);
                if (d >= b) break;
            }
            if (d < b) best[o] = d;
        }
    }
    if (allm && u >= 0) {
        float m = 3.402823466e38f;
        for (int dy = 0; dy < K; ++dy) {
            for (int dx = 0; dx < K; ++dx) {
                const float* pg = prev + ((gy + dy - md) * WW + (gx + dx - md)) * CC;
                float d = 0.0f;
                for (int c = 0; c < CC; c += 4) {
                    const float4 pv = __ldg((const float4*)(pg + c));
                    const float4 qv = __ldg((const float4*)(qp + c));
                    d = dist4s(qv, pv, d);
                    if (d >= m) break;
                }
                if (d < m) m = d;
            }
        }
        best[u] = m;
    }
    float* op = out + (gy * WW + gx) * nobj;
    for (int t = 0; t < no; t++) op[t] = best[t];
    for (int t = no; t < nobj; t++) op[t] = 1.0f;
}

extern "C" void kernel_launch(void* const* d_in, const int* in_sizes, int n_in,
                              void* d_out, int out_size) {
    // metadata order: prev_frame_embedding, query_embedding, prev_frame_labels,
    //                 gt_ids, max_distance
    const float* prev   = (const float*)d_in[0];
    const float* query  = (const float*)d_in[1];
    const int*   labels = (const int*)d_in[2];
    const int*   gt     = (const int*)d_in[3];
    const int*   mdp    = (n_in >= 5) ? (const int*)d_in[4] : nullptr;
    const int    nobj   = in_sizes[3];

    dim3 grid(WW / TX, HH / TY);   // 16 x 32 = 512 CTAs
    IntVOS_27015344292341_kernel<<<grid, NTHREADS>>>(
        prev, query, labels, gt, mdp, (float*)d_out, nobj);
}